// round 11
// baseline (speedup 1.0000x reference)
#include <cuda_runtime.h>

// DynamicLIF persistent kernel for GB300 (sm_103a), round 11.
// Base = R10 (65.0us: coordinator-side MLP, packed gen|tau release).
// CHANGE: 512-thread streaming blocks, 8 per batch (grid 288 = 256 + 32
// coordinators), __launch_bounds__(512,2) -> 2 CTA/SM, capacity 296 >= 288.
//  - oe drops 4->2: oe*MLP_p1 = 16 ~ Q_th, killing the cross-CTA L1tex
//    queue-contention spread term (B300 spread model).
//  - Per-batch barrier max is over 8 blocks instead of 16.
// Channel mapping = R4's 512-thread layout (benched rel_err 0.0): slice i
// holds channels 2i (warps 0-7) and 2i+1 (warps 8-15); identical
// lane->element offsets and warp-order summation -> channel sums
// bit-identical. Coordinator MLP byte-identical to R10.

#define NB 32          // batch
#define NT 8           // time steps
#define NC 128         // channels
#define HW_ 1024       // H*W
#define CR 32          // C / red
#define THREADS 512
#define RPB 8          // float4 slices per thread
#define CPB 16         // channels per block
#define BPB 8          // streaming blocks per batch
#define NSTREAM (NB * BPB)       // 256
#define NBLOCKS (NSTREAM + NB)   // 288 (32 coordinators)
#define PUBS (BPB * CPB)         // 128 count-releases per batch per step
#define CPAD 64        // 256B stride for g_count (unsigned)
#define SPAD 32        // 256B stride for g_sync (u64)

__device__ float              g_sums[NB * NC];
__device__ unsigned           g_count[NB * CPAD]; // zero at launch; coord resets at end
__device__ unsigned long long g_sync[NB * SPAD];  // (gen<<32)|tau_bits, monotonic gen

__device__ __forceinline__ unsigned ld_acquire_u32(const unsigned* p) {
    unsigned v;
    asm volatile("ld.acquire.gpu.global.u32 %0, [%1];" : "=r"(v) : "l"(p));
    return v;
}
__device__ __forceinline__ unsigned long long ld_acquire_u64(const unsigned long long* p) {
    unsigned long long v;
    asm volatile("ld.acquire.gpu.global.u64 %0, [%1];" : "=l"(v) : "l"(p));
    return v;
}
__device__ __forceinline__ void st_release_u64(unsigned long long* p, unsigned long long v) {
    asm volatile("st.release.gpu.global.u64 [%0], %1;" :: "l"(p), "l"(v));
}
__device__ __forceinline__ void red_release_add(unsigned* p, unsigned v) {
    asm volatile("red.release.gpu.global.add.u32 [%0], %1;" :: "l"(p), "r"(v));
}

__global__ void __launch_bounds__(THREADS, 2)
lif_kernel(const float* __restrict__ x,
           const float* __restrict__ w1,
           const float* __restrict__ b1,
           const float* __restrict__ w2,
           const float* __restrict__ b2,
           float* __restrict__ out)
{
    const int tid = threadIdx.x;
    const int blk = blockIdx.x;
    const int lane = tid & 31;
    const int warp = tid >> 5;

    // ---------------- coordinator blocks (one per batch) ----------------
    if (blk >= NSTREAM) {
        __shared__ float s_w1t[NC * CR];   // 16 KB, TRANSPOSED: [c][row]
        __shared__ float s_mean[NC];

        const int bb = blk - NSTREAM;
        unsigned*           cnt = &g_count[bb * CPAD];
        unsigned long long* syn = &g_sync[bb * SPAD];

        // Cache w1 transposed (conflict-free MLP reads).
        #pragma unroll
        for (int i = 0; i < (CR * NC) / THREADS; i++) {
            int idx = i * THREADS + tid;
            s_w1t[(idx & 127) * CR + (idx >> 7)] = w1[idx];
        }

        unsigned base_gen = 0;
        if (tid == 0) base_gen = (unsigned)(*(volatile unsigned long long*)syn >> 32);
        __syncthreads();

        #pragma unroll 1
        for (int t = 0; t < NT - 1; t++) {
            // Wait for all 128 publishes of step t.
            if (tid == 0) {
                unsigned tgt = (unsigned)PUBS * (unsigned)(t + 1);
                while (ld_acquire_u32(cnt) < tgt) { }
            }
            __syncthreads();   // acquire by t0 + barrier -> sums visible

            // MLP: values + order byte-identical to R10.
            if (tid < NC)
                s_mean[tid] = __ldcg(&g_sums[bb * NC + tid]) * (1.0f / 1024.0f);
            __syncthreads();
            if (tid < CR) {
                float acc = b1[tid];
                #pragma unroll
                for (int c = 0; c < NC; c++)
                    acc = fmaf(s_w1t[c * CR + tid], s_mean[c], acc);
                float e = fmaxf(acc, 0.0f);        // relu
                float p = e * w2[tid];
                p += __shfl_xor_sync(0xffffffffu, p, 16);
                p += __shfl_xor_sync(0xffffffffu, p, 8);
                p += __shfl_xor_sync(0xffffffffu, p, 4);
                p += __shfl_xor_sync(0xffffffffu, p, 2);
                p += __shfl_xor_sync(0xffffffffu, p, 1);
                if (tid == 0) {
                    float z = p + b2[0];
                    float tn = 1.0f / (1.0f + expf(-z));   // sigmoid
                    unsigned long long v =
                        ((unsigned long long)(base_gen + (unsigned)(t + 1)) << 32)
                        | (unsigned long long)__float_as_uint(tn);
                    st_release_u64(syn, v);   // gen + tau in one word
                }
            }
            __syncthreads();
        }
        // All publishes observed -> no publisher remains. Reset for the next
        // graph replay (ordered by kernel completion boundary).
        if (tid == 0) *(volatile unsigned*)cnt = 0;
        return;
    }

    // ---------------- streaming blocks ----------------
    __shared__ float s_warp[16][RPB];
    __shared__ float s_tau;

    const int b   = blk >> 3;          // batch (blk / BPB)
    const int sub = blk & 7;           // sub-block within batch
    unsigned*           const cnt = &g_count[b * CPAD];
    unsigned long long* const syn = &g_sync[b * SPAD];

    // base_gen read precedes this block's first publish (program order), and
    // no release can happen until all 8 blocks publish -> race-free across
    // startup skew AND graph replays.
    unsigned base_gen = 0;
    if (tid == 0) base_gen = (unsigned)(*(volatile unsigned long long*)syn >> 32);

    float tau = 0.5f;                  // TAU0
    float4 mem[RPB];
    #pragma unroll
    for (int i = 0; i < RPB; i++) mem[i] = make_float4(0.f, 0.f, 0.f, 0.f);

    // This block owns channels [sub*CPB, sub*CPB+CPB) of batch b, all HW.
    const size_t row_base = ((size_t)b * NT * NC + (size_t)sub * CPB) * HW_;

    for (int t = 0; t < NT; t++) {
        const float4* xp = (const float4*)(x   + row_base + (size_t)t * NC * HW_);
        float4*       op = (float4*)      (out + row_base + (size_t)t * NC * HW_);

        // ---- 1) mem = mem*tau + x  (separate mul+add: matches JAX rounding),
        //         per-slice partial sums. Bit-identical to R4's mapping. ----
        float part[RPB];
        #pragma unroll
        for (int i = 0; i < RPB; i++) {
            float4 xv = __ldcs(xp + i * THREADS + tid);
            float4 m = mem[i];
            m.x = __fadd_rn(__fmul_rn(m.x, tau), xv.x);
            m.y = __fadd_rn(__fmul_rn(m.y, tau), xv.y);
            m.z = __fadd_rn(__fmul_rn(m.z, tau), xv.z);
            m.w = __fadd_rn(__fmul_rn(m.w, tau), xv.w);
            mem[i] = m;
            part[i] = (m.x + m.y) + (m.z + m.w);
        }

        const bool need_tau = (t < NT - 1);   // last step: no publish/wait

        if (need_tau) {
            // Warp-reduce each slice partial (identical shfl order).
            #pragma unroll
            for (int i = 0; i < RPB; i++) {
                float v = part[i];
                v += __shfl_xor_sync(0xffffffffu, v, 16);
                v += __shfl_xor_sync(0xffffffffu, v, 8);
                v += __shfl_xor_sync(0xffffffffu, v, 4);
                v += __shfl_xor_sync(0xffffffffu, v, 2);
                v += __shfl_xor_sync(0xffffffffu, v, 1);
                if (lane == 0) s_warp[warp][i] = v;
            }
            __syncthreads();
            // Publish this block's 16 channel sums. Slice i holds channels
            // 2i (warps 0-7) and 2i+1 (warps 8-15); warp-order summation.
            if (tid < CPB) {
                const int lc = tid;
                const int i  = lc >> 1;
                const int wb = (lc & 1) * 8;
                float s = 0.f;
                #pragma unroll
                for (int w = 0; w < 8; w++) s += s_warp[wb + w][i];
                __stcg(&g_sums[b * NC + sub * CPB + lc], s);
                red_release_add(cnt, 1u);
            }
        }

        // ---- 2) spike + output + soft reset (overlaps coordinator MLP) ----
        #pragma unroll
        for (int i = 0; i < RPB; i++) {
            float4 m = mem[i];
            float4 sp;
            sp.x = (m.x > 1.0f) ? 1.0f : 0.0f;
            sp.y = (m.y > 1.0f) ? 1.0f : 0.0f;
            sp.z = (m.z > 1.0f) ? 1.0f : 0.0f;
            sp.w = (m.w > 1.0f) ? 1.0f : 0.0f;
            __stcs(op + i * THREADS + tid, sp);
            m.x = (m.x > 1.0f) ? 0.0f : m.x;
            m.y = (m.y > 1.0f) ? 0.0f : m.y;
            m.z = (m.z > 1.0f) ? 0.0f : m.z;
            m.w = (m.w > 1.0f) ? 0.0f : m.w;
            mem[i] = m;
        }

        if (!need_tau) break;

        // ---- 3) single poll: generation + tau arrive together ----
        if (tid == 0) {
            unsigned tgt = base_gen + (unsigned)(t + 1);
            unsigned long long v;
            do {
                v = ld_acquire_u64(syn);
            } while ((int)((unsigned)(v >> 32) - tgt) < 0);
            s_tau = __uint_as_float((unsigned)v);
        }
        __syncthreads();
        tau = s_tau;
    }
}

extern "C" void kernel_launch(void* const* d_in, const int* in_sizes, int n_in,
                              void* d_out, int out_size)
{
    const float* x  = (const float*)d_in[0];
    const float* w1 = (const float*)d_in[1];
    const float* b1 = (const float*)d_in[2];
    const float* w2 = (const float*)d_in[3];
    const float* b2 = (const float*)d_in[4];
    float* out = (float*)d_out;

    lif_kernel<<<NBLOCKS, THREADS>>>(x, w1, b1, w2, b2, out);
}